// round 7
// baseline (speedup 1.0000x reference)
#include <cuda_runtime.h>
#include <math.h>

#define EPS_F      1e-6f
#define LOG_BIAS_F 1.0f
#define W_DIM      32
#define H_DIM      12
#define NREG       (W_DIM + 1)
#define ASTRIDE    13            // >= H_DIM, odd stride avoids systematic bank conflicts
#define MAX_S      4096

// Scratch tables (allocation-free: __device__ globals)
__device__ float  g_logrel[MAX_S];       // log(|d|*c + bias + eps)
__device__ float  g_invln[MAX_S];        // 1 / log(|c*pos_norm(s)| + bias + eps)
__device__ float  g_brk[W_DIM];          // sorted ReLU breakpoints
__device__ float2 g_AB[NREG * ASTRIDE];  // per-region (slope, offset) per head
__device__ int    g_ready;               // monotonic flag; setup idempotent per call

__device__ __forceinline__ int pwl_region(const float* s_brk, float x)
{
    int r = 0;
    #pragma unroll
    for (int step = 32; step >= 1; step >>= 1)
        if (r + step <= W_DIM && s_brk[r + step - 1] < x) r += step;
    return r;
}

// ---------------------------------------------------------------------------
// Fused kernel. Block (0,0) builds all tables (256-thread parallel, ~1-2us),
// release-fences, raises g_ready, then does its own tile. Other blocks spin
// on g_ready via L2 atomics (NO reader-side __threadfence — it emits
// CCTL.IVALL and flushes L1 per block; safe to omit since atomics bypass L1
// and no SM caches table lines pre-flag on the first call).
// Hot loop: region-coherence fast path — the 4 t's of a thread nearly always
// share a PWL region, so search twice (nd[0], nd[3]) and load 12 AB pairs.
// ---------------------------------------------------------------------------
__global__ void __launch_bounds__(256, 6)
fire_fused_kernel(const float* __restrict__ w1,
                  const float* __restrict__ b1,
                  const float* __restrict__ w2,   // [H, W]
                  const float* __restrict__ b2,
                  const float* __restrict__ c_p,
                  const float* __restrict__ lm_p,
                  const float* __restrict__ il_p,
                  float* __restrict__ out, int S)
{
    const int tid = threadIdx.x;
    const bool is_setup = (blockIdx.x == 0) && (blockIdx.y == 0);

    __shared__ float  s_brk[W_DIM];
    __shared__ float2 s_AB[NREG * ASTRIDE];

    if (is_setup) {
        // ---- 1-D log tables ----
        const float c   = c_p[0];
        const float thr = fabsf(lm_p[0] * il_p[0]);
        for (int d = tid; d < S; d += blockDim.x)
            g_logrel[d] = logf(((float)d + EPS_F) * c + LOG_BIAS_F + EPS_F);
        for (int ss = tid; ss < S; ss += blockDim.x) {
            float pn = fmaxf((float)ss, thr) + EPS_F;
            g_invln[ss] = 1.0f / logf(fabsf(c * pn) + LOG_BIAS_F + EPS_F);
        }

        // ---- breakpoints + stable ranks (32 threads) ----
        __shared__ float sw_w1v[W_DIM];
        __shared__ float sw_b1[W_DIM];
        __shared__ float sw_brk[W_DIM];
        __shared__ int   sw_rank[W_DIM];
        if (tid < W_DIM) {
            float a = w1[tid];
            if (a == 0.0f) a = 1e-30f;      // constant-relu -> far breakpoint
            sw_w1v[tid] = a;
            sw_b1[tid]  = b1[tid];
            sw_brk[tid] = -b1[tid] / a;
        }
        __syncthreads();
        if (tid < W_DIM) {
            const float mine = sw_brk[tid];
            int r = 0;
            #pragma unroll
            for (int j = 0; j < W_DIM; j++) {
                float bj = sw_brk[j];
                r += (bj < mine) || (bj == mine && j < tid);
            }
            sw_rank[tid] = r;
            g_brk[r] = mine;
        }
        __syncthreads();

        // ---- 33x12 region coefficients (one (r,h) per thread) ----
        // Region r: nd above breakpoints of rank < r.
        // Unit w active iff (w1>0 && rank<r) || (w1<0 && rank>=r).
        for (int p = tid; p < NREG * H_DIM; p += blockDim.x) {
            const int r = p / H_DIM;
            const int h = p % H_DIM;
            float A = 0.0f, B = b2[h];
            #pragma unroll
            for (int w = 0; w < W_DIM; w++) {
                const float w1v = sw_w1v[w];
                const bool active = (w1v > 0.0f) ? (sw_rank[w] < r)
                                                 : (sw_rank[w] >= r);
                if (active) {
                    const float w2v = w2[h * W_DIM + w];
                    A += w1v      * w2v;
                    B += sw_b1[w] * w2v;
                }
            }
            g_AB[r * ASTRIDE + h] = make_float2(A, B);
        }

        __threadfence();                    // release: publish tables
        __syncthreads();
        if (tid == 0) atomicExch(&g_ready, 1);
    } else {
        if (tid == 0) {
            while (atomicAdd(&g_ready, 0) == 0) __nanosleep(64);
        }
        __syncthreads();
    }

    // ---- Stage block-local copies of the PWL model ----
    if (tid < W_DIM) s_brk[tid] = __ldg(&g_brk[tid]);
    for (int i = tid; i < NREG * ASTRIDE; i += blockDim.x)
        s_AB[i] = __ldg(&g_AB[i]);
    __syncthreads();

    // ---- Output tile ----
    const int s  = blockIdx.y;
    const int t0 = (blockIdx.x * blockDim.x + tid) * 4;
    if (t0 >= S) return;

    const float invln = __ldg(&g_invln[s]);
    const int nvalid = (S - t0 >= 4) ? 4 : (S - t0);

    float nd[4];
    #pragma unroll
    for (int i = 0; i < 4; i++) {
        int t = t0 + i;
        int d = (t < S) ? abs(s - t) : 0;
        nd[i] = __ldg(&g_logrel[d]) * invln;
    }

    const size_t SS  = (size_t)S * (size_t)S;
    const size_t row = (size_t)s * (size_t)S + (size_t)t0;

    const int r0 = pwl_region(s_brk, nd[0]);
    const int r3 = pwl_region(s_brk, nd[3]);

    if (nvalid == 4) {
        float* o = out + row;
        if (r0 == r3) {
            // Fast path (>98% of threads): one region for all 4 elements.
            const int b0 = r0 * ASTRIDE;
            #pragma unroll
            for (int h = 0; h < H_DIM; h++) {
                const float2 ab = s_AB[b0 + h];
                __stcs(reinterpret_cast<float4*>(o + (size_t)h * SS),
                       make_float4(fmaf(ab.x, nd[0], ab.y),
                                   fmaf(ab.x, nd[1], ab.y),
                                   fmaf(ab.x, nd[2], ab.y),
                                   fmaf(ab.x, nd[3], ab.y)));
            }
        } else {
            int base[4];
            base[0] = r0 * ASTRIDE;
            base[1] = pwl_region(s_brk, nd[1]) * ASTRIDE;
            base[2] = pwl_region(s_brk, nd[2]) * ASTRIDE;
            base[3] = r3 * ASTRIDE;
            #pragma unroll
            for (int h = 0; h < H_DIM; h++) {
                float v[4];
                #pragma unroll
                for (int i = 0; i < 4; i++) {
                    const float2 ab = s_AB[base[i] + h];
                    v[i] = fmaf(ab.x, nd[i], ab.y);
                }
                __stcs(reinterpret_cast<float4*>(o + (size_t)h * SS),
                       make_float4(v[0], v[1], v[2], v[3]));
            }
        }
    } else {
        for (int h = 0; h < H_DIM; h++)
            for (int i = 0; i < nvalid; i++) {
                const int b = pwl_region(s_brk, nd[i]) * ASTRIDE;
                const float2 ab = s_AB[b + h];
                out[(size_t)h * SS + row + i] = fmaf(ab.x, nd[i], ab.y);
            }
    }
}

// ---------------------------------------------------------------------------
// Launch
// Inputs (metadata order): x, w1, b1, w2, b2, c, L_multiplier, init_L
// ---------------------------------------------------------------------------
extern "C" void kernel_launch(void* const* d_in, const int* in_sizes, int n_in,
                              void* d_out, int out_size)
{
    const float* w1 = (const float*)d_in[1];
    const float* b1 = (const float*)d_in[2];
    const float* w2 = (const float*)d_in[3];
    const float* b2 = (const float*)d_in[4];
    const float* c  = (const float*)d_in[5];
    const float* lm = (const float*)d_in[6];
    const float* il = (const float*)d_in[7];
    float* out = (float*)d_out;

    const int H = in_sizes[4];                       // 12
    int S = (int)(sqrt((double)(out_size / H)) + 0.5);
    if (S > MAX_S) S = MAX_S;                        // safety clamp

    const int groups = (S + 3) / 4;                  // t-groups per row
    dim3 block(256);
    dim3 grid((groups + 255) / 256, S);
    fire_fused_kernel<<<grid, block>>>(w1, b1, w2, b2, c, lm, il, out, S);
}

// round 8
// speedup vs baseline: 1.1692x; 1.1692x over previous
#include <cuda_runtime.h>
#include <math.h>

#define EPS_F      1e-6f
#define LOG_BIAS_F 1.0f
#define W_DIM      32
#define H_DIM      12
#define NREG       (W_DIM + 1)
#define ASTRIDE    13            // >= H_DIM, odd stride avoids systematic bank conflicts
#define MAX_S      4096

// Scratch tables (allocation-free: __device__ globals)
__device__ float  g_logrel[MAX_S];       // log(|d|*c + bias + eps)
__device__ float  g_invln[MAX_S];        // 1 / log(|c*pos_norm(s)| + bias + eps)
__device__ float  g_brk[W_DIM];          // sorted ReLU breakpoints
__device__ float2 g_AB[NREG * ASTRIDE];  // per-region (slope, offset) per head
__device__ int    g_ready;               // monotonic flag; setup idempotent per call

// ---------------------------------------------------------------------------
// Fused kernel, 1-D grid of (1 + S*groupsPerRow) blocks.
//  Block 0: DEDICATED setup block — builds tables (256-thread parallel),
//  release-fences, raises g_ready, and EXITS (no tile). This removes the
//  straggler effect where the setup block's ~2us prologue delayed the last
//  wave (R6 kernel 33.25us vs standalone main 31.78us).
//  Blocks >= 1: spin on g_ready via L2 atomics (waits only on the very first
//  call of the run; g_ready stays 1 across graph replays while the rebuild
//  each call keeps outputs deterministic). NO reader-side __threadfence —
//  that emits CCTL.IVALL (per-block L1 flush, the R4 regression). Safe:
//  atomics bypass L1 and no SM caches table lines pre-flag on call 1.
//  Hot loop = R6's proven uniform loop: 4 nd per thread, branchless region
//  search, 48 LDS.64 + 48 FMA, 12 coalesced float4 streaming stores.
// ---------------------------------------------------------------------------
__global__ void __launch_bounds__(256, 6)
fire_fused_kernel(const float* __restrict__ w1,
                  const float* __restrict__ b1,
                  const float* __restrict__ w2,   // [H, W]
                  const float* __restrict__ b2,
                  const float* __restrict__ c_p,
                  const float* __restrict__ lm_p,
                  const float* __restrict__ il_p,
                  float* __restrict__ out, int S, int groupsPerRow)
{
    const int tid = threadIdx.x;
    const int bid = blockIdx.x;

    if (bid == 0) {
        // ---- Dedicated setup block ----
        const float c   = c_p[0];
        const float thr = fabsf(lm_p[0] * il_p[0]);
        for (int d = tid; d < S; d += blockDim.x)
            g_logrel[d] = logf(((float)d + EPS_F) * c + LOG_BIAS_F + EPS_F);
        for (int ss = tid; ss < S; ss += blockDim.x) {
            float pn = fmaxf((float)ss, thr) + EPS_F;
            g_invln[ss] = 1.0f / logf(fabsf(c * pn) + LOG_BIAS_F + EPS_F);
        }

        __shared__ float sw_w1v[W_DIM];
        __shared__ float sw_b1[W_DIM];
        __shared__ float sw_brk[W_DIM];
        __shared__ int   sw_rank[W_DIM];
        if (tid < W_DIM) {
            float a = w1[tid];
            if (a == 0.0f) a = 1e-30f;      // constant-relu -> far breakpoint
            sw_w1v[tid] = a;
            sw_b1[tid]  = b1[tid];
            sw_brk[tid] = -b1[tid] / a;
        }
        __syncthreads();
        if (tid < W_DIM) {
            const float mine = sw_brk[tid];
            int r = 0;
            #pragma unroll
            for (int j = 0; j < W_DIM; j++) {
                float bj = sw_brk[j];
                r += (bj < mine) || (bj == mine && j < tid);   // stable rank
            }
            sw_rank[tid] = r;
            g_brk[r] = mine;
        }
        __syncthreads();

        // 33x12 region coefficients. Region r: nd above breakpoints of rank<r.
        // Unit w active iff (w1>0 && rank<r) || (w1<0 && rank>=r).
        for (int p = tid; p < NREG * H_DIM; p += blockDim.x) {
            const int r = p / H_DIM;
            const int h = p % H_DIM;
            float A = 0.0f, B = b2[h];
            #pragma unroll
            for (int w = 0; w < W_DIM; w++) {
                const float w1v = sw_w1v[w];
                const bool active = (w1v > 0.0f) ? (sw_rank[w] < r)
                                                 : (sw_rank[w] >= r);
                if (active) {
                    const float w2v = w2[h * W_DIM + w];
                    A += w1v      * w2v;
                    B += sw_b1[w] * w2v;
                }
            }
            g_AB[r * ASTRIDE + h] = make_float2(A, B);
        }

        __threadfence();                    // release: publish tables
        __syncthreads();
        if (tid == 0) atomicExch(&g_ready, 1);
        return;                             // no tile work
    }

    // ---- Worker blocks ----
    if (tid == 0) {
        while (atomicAdd(&g_ready, 0) == 0) __nanosleep(64);
    }
    __syncthreads();

    __shared__ float  s_brk[W_DIM];
    __shared__ float2 s_AB[NREG * ASTRIDE];
    if (tid < W_DIM) s_brk[tid] = __ldg(&g_brk[tid]);
    for (int i = tid; i < NREG * ASTRIDE; i += blockDim.x)
        s_AB[i] = __ldg(&g_AB[i]);
    __syncthreads();

    const int q  = bid - 1;
    const int s  = q / groupsPerRow;
    const int gx = q - s * groupsPerRow;
    const int t0 = (gx * 256 + tid) * 4;
    if (t0 >= S) return;

    const float invln = __ldg(&g_invln[s]);
    const int nvalid = (S - t0 >= 4) ? 4 : (S - t0);

    float nd[4];
    int   base[4];
    #pragma unroll
    for (int i = 0; i < 4; i++) {
        int t = t0 + i;
        int d = (t < S) ? abs(s - t) : 0;
        nd[i] = __ldg(&g_logrel[d]) * invln;
    }
    #pragma unroll
    for (int i = 0; i < 4; i++) {
        const float x = nd[i];
        int r = 0;
        #pragma unroll
        for (int step = 32; step >= 1; step >>= 1)
            if (r + step <= W_DIM && s_brk[r + step - 1] < x) r += step;
        base[i] = r * ASTRIDE;
    }

    const size_t SS  = (size_t)S * (size_t)S;
    const size_t row = (size_t)s * (size_t)S + (size_t)t0;

    if (nvalid == 4) {
        float* o = out + row;
        #pragma unroll
        for (int h = 0; h < H_DIM; h++) {
            float v[4];
            #pragma unroll
            for (int i = 0; i < 4; i++) {
                const float2 ab = s_AB[base[i] + h];
                v[i] = fmaf(ab.x, nd[i], ab.y);
            }
            __stcs(reinterpret_cast<float4*>(o + (size_t)h * SS),
                   make_float4(v[0], v[1], v[2], v[3]));
        }
    } else {
        for (int h = 0; h < H_DIM; h++)
            for (int i = 0; i < nvalid; i++) {
                const float2 ab = s_AB[base[i] + h];
                out[(size_t)h * SS + row + i] = fmaf(ab.x, nd[i], ab.y);
            }
    }
}

// ---------------------------------------------------------------------------
// Launch
// Inputs (metadata order): x, w1, b1, w2, b2, c, L_multiplier, init_L
// ---------------------------------------------------------------------------
extern "C" void kernel_launch(void* const* d_in, const int* in_sizes, int n_in,
                              void* d_out, int out_size)
{
    const float* w1 = (const float*)d_in[1];
    const float* b1 = (const float*)d_in[2];
    const float* w2 = (const float*)d_in[3];
    const float* b2 = (const float*)d_in[4];
    const float* c  = (const float*)d_in[5];
    const float* lm = (const float*)d_in[6];
    const float* il = (const float*)d_in[7];
    float* out = (float*)d_out;

    const int H = in_sizes[4];                       // 12
    int S = (int)(sqrt((double)(out_size / H)) + 0.5);
    if (S > MAX_S) S = MAX_S;                        // safety clamp

    const int groupsPerRow = (S + 1023) / 1024;      // 1024 t per block
    const int nblocks = 1 + S * groupsPerRow;        // block 0 = setup only
    fire_fused_kernel<<<nblocks, 256>>>(w1, b1, w2, b2, c, lm, il, out,
                                        S, groupsPerRow);
}